// round 4
// baseline (speedup 1.0000x reference)
#include <cuda_runtime.h>
#include <math.h>

#define A_N 1000
#define N_N 2000
#define Z_N 2000
#define D_N 8

// ---------------- device scratch (no cudaMalloc allowed) ----------------
__device__ float g_T1[N_N * Z_N];        // K @ B
__device__ float g_T2[N_N * Z_N];        // K @ K @ B
__device__ float g_gX[N_N * Z_N];        // gamma_X
__device__ float g_E1c[A_N * N_N];
__device__ float g_E1s[A_N * N_N];
__device__ float g_E2c[A_N * N_N];
__device__ float g_E2s[A_N * N_N];
__device__ float g_den[4 * A_N * Z_N];   // planes: inv|p|^2, inv|q|^2, r_re, r_im
__device__ float g_acc;

__global__ void zero_acc_kernel() { g_acc = 0.f; }

// ---------------- phase features: cos/sin of alpha @ N^T and alpha @ X^T ----------------
__global__ void trig_kernel(const float* __restrict__ alpha,
                            const float* __restrict__ Nmat,
                            const float* __restrict__ Xmat) {
  int idx = blockIdx.x * blockDim.x + threadIdx.x;
  if (idx >= A_N * N_N) return;
  int a = idx / N_N;
  int j = idx - a * N_N;
  float ph1 = 0.f, ph2 = 0.f;
#pragma unroll
  for (int d = 0; d < D_N; d++) {
    float al = alpha[a * D_N + d];
    ph1 = fmaf(al, Nmat[j * D_N + d], ph1);
    ph2 = fmaf(al, Xmat[j * D_N + d], ph2);
  }
  float s1, c1, s2, c2;
  sincosf(ph1, &s1, &c1);
  sincosf(ph2, &s2, &c2);
  g_E1c[idx] = c1;
  g_E1s[idx] = s1;
  g_E2c[idx] = c2;
  g_E2s[idx] = s2;
}

// ---------------- fp32 SGEMM 2000x2000x2000 (Neumann terms) ----------------
__global__ __launch_bounds__(256) void sgemm2000(const float* __restrict__ A,
                                                 const float* __restrict__ B,
                                                 float* __restrict__ C) {
  const int M = N_N, N = Z_N, K = N_N;
  __shared__ float As[8][128];
  __shared__ float Bs[8][128];
  int tid = threadIdx.x;
  int brow = blockIdx.y * 128;
  int bcol = blockIdx.x * 128;
  int trow = (tid / 16) * 8;
  int tcol = (tid % 16) * 8;
  int arow = tid >> 1;
  int acol = (tid & 1) * 4;
  int browl = tid >> 5;
  int bcoll = (tid & 31) * 4;
  float acc[8][8];
#pragma unroll
  for (int i = 0; i < 8; i++)
#pragma unroll
    for (int j = 0; j < 8; j++) acc[i][j] = 0.f;

  const float4 zf4 = make_float4(0.f, 0.f, 0.f, 0.f);
  for (int k0 = 0; k0 < K; k0 += 8) {
    int gr = brow + arow;
    float4 av = (gr < M) ? *reinterpret_cast<const float4*>(&A[gr * K + k0 + acol]) : zf4;
    As[acol + 0][arow] = av.x;
    As[acol + 1][arow] = av.y;
    As[acol + 2][arow] = av.z;
    As[acol + 3][arow] = av.w;
    int gc = bcol + bcoll;
    float4 bv = (gc < N) ? *reinterpret_cast<const float4*>(&B[(k0 + browl) * N + gc]) : zf4;
    *reinterpret_cast<float4*>(&Bs[browl][bcoll]) = bv;
    __syncthreads();
#pragma unroll
    for (int kk = 0; kk < 8; kk++) {
      float ar[8], br[8];
#pragma unroll
      for (int i = 0; i < 8; i++) ar[i] = As[kk][trow + i];
#pragma unroll
      for (int j = 0; j < 8; j++) br[j] = Bs[kk][tcol + j];
#pragma unroll
      for (int i = 0; i < 8; i++)
#pragma unroll
        for (int j = 0; j < 8; j++) acc[i][j] = fmaf(ar[i], br[j], acc[i][j]);
    }
    __syncthreads();
  }
#pragma unroll
  for (int i = 0; i < 8; i++) {
    int r = brow + trow + i;
    if (r >= M) continue;
#pragma unroll
    for (int j = 0; j < 8; j++) {
      int c = bcol + tcol + j;
      if (c < N) C[r * N + c] = acc[i][j];
    }
  }
}

// gamma_X = (B - T1/c + T2/c^2)/c,  c = n * exp(log_lambda)
__global__ void combine_gamma_kernel(const float* __restrict__ B,
                                     const float* __restrict__ loglam) {
  int i = blockIdx.x * blockDim.x + threadIdx.x;
  if (i >= N_N * Z_N) return;
  float c = (float)N_N * expf(loglam[0]);
  float ic = 1.f / c;
  g_gX[i] = (B[i] - (g_T1[i] - g_T2[i] * ic) * ic) * ic;
}

#define LD4(dst, src)                                     \
  {                                                       \
    float4 _t = *reinterpret_cast<const float4*>(src);    \
    (dst)[0] = _t.x; (dst)[1] = _t.y;                     \
    (dst)[2] = _t.z; (dst)[3] = _t.w;                     \
  }

// ---------------- denominators: p = E1 @ gamma_N, q = E2 @ gamma_X ----------------
__global__ __launch_bounds__(256) void denom_kernel(const float* __restrict__ gammaN) {
  __shared__ float sE1c[16][64];
  __shared__ float sE1s[16][64];
  __shared__ float sE2c[16][64];
  __shared__ float sE2s[16][64];
  __shared__ float sGn[16][64];
  __shared__ float sGx[16][64];
  int tid = threadIdx.x;
  int ablk = blockIdx.y * 64;
  int zblk = blockIdx.x * 64;
  int ta = (tid / 16) * 4;
  int tz = (tid % 16) * 4;
  int e_ar = tid >> 2;
  int e_kc = (tid & 3) * 4;
  int g_kr = tid >> 4;
  int g_zc = (tid & 15) * 4;
  int ga = ablk + e_ar;
  bool a_ok = (ga < A_N);
  int gz = zblk + g_zc;
  bool z_ok = (gz < Z_N);
  const float4 zf4 = make_float4(0.f, 0.f, 0.f, 0.f);

  float pr[4][4], pim[4][4], qr[4][4], qim[4][4];
#pragma unroll
  for (int i = 0; i < 4; i++)
#pragma unroll
    for (int j = 0; j < 4; j++) { pr[i][j] = 0.f; pim[i][j] = 0.f; qr[i][j] = 0.f; qim[i][j] = 0.f; }

  for (int k0 = 0; k0 < N_N; k0 += 16) {
    int eoff = ga * N_N + k0 + e_kc;
    float4 t;
    t = a_ok ? *reinterpret_cast<const float4*>(&g_E1c[eoff]) : zf4;
    sE1c[e_kc + 0][e_ar] = t.x; sE1c[e_kc + 1][e_ar] = t.y; sE1c[e_kc + 2][e_ar] = t.z; sE1c[e_kc + 3][e_ar] = t.w;
    t = a_ok ? *reinterpret_cast<const float4*>(&g_E1s[eoff]) : zf4;
    sE1s[e_kc + 0][e_ar] = t.x; sE1s[e_kc + 1][e_ar] = t.y; sE1s[e_kc + 2][e_ar] = t.z; sE1s[e_kc + 3][e_ar] = t.w;
    t = a_ok ? *reinterpret_cast<const float4*>(&g_E2c[eoff]) : zf4;
    sE2c[e_kc + 0][e_ar] = t.x; sE2c[e_kc + 1][e_ar] = t.y; sE2c[e_kc + 2][e_ar] = t.z; sE2c[e_kc + 3][e_ar] = t.w;
    t = a_ok ? *reinterpret_cast<const float4*>(&g_E2s[eoff]) : zf4;
    sE2s[e_kc + 0][e_ar] = t.x; sE2s[e_kc + 1][e_ar] = t.y; sE2s[e_kc + 2][e_ar] = t.z; sE2s[e_kc + 3][e_ar] = t.w;

    int goff = (k0 + g_kr) * Z_N + gz;
    float4 gn = z_ok ? *reinterpret_cast<const float4*>(&gammaN[goff]) : zf4;
    *reinterpret_cast<float4*>(&sGn[g_kr][g_zc]) = gn;
    float4 gx = z_ok ? *reinterpret_cast<const float4*>(&g_gX[goff]) : zf4;
    *reinterpret_cast<float4*>(&sGx[g_kr][g_zc]) = gx;
    __syncthreads();

#pragma unroll
    for (int kk = 0; kk < 16; kk++) {
      float e1c[4], e1s[4], e2c[4], e2s[4], gn4[4], gx4[4];
      LD4(e1c, &sE1c[kk][ta]);
      LD4(e1s, &sE1s[kk][ta]);
      LD4(e2c, &sE2c[kk][ta]);
      LD4(e2s, &sE2s[kk][ta]);
      LD4(gn4, &sGn[kk][tz]);
      LD4(gx4, &sGx[kk][tz]);
#pragma unroll
      for (int i = 0; i < 4; i++)
#pragma unroll
        for (int j = 0; j < 4; j++) {
          pr[i][j]  = fmaf(e1c[i], gn4[j], pr[i][j]);
          pim[i][j] = fmaf(e1s[i], gn4[j], pim[i][j]);
          qr[i][j]  = fmaf(e2c[i], gx4[j], qr[i][j]);
          qim[i][j] = fmaf(e2s[i], gx4[j], qim[i][j]);
        }
    }
    __syncthreads();
  }

  const int PL = A_N * Z_N;
#pragma unroll
  for (int i = 0; i < 4; i++) {
    int a = ablk + ta + i;
    if (a >= A_N) continue;
#pragma unroll
    for (int j = 0; j < 4; j++) {
      int z = zblk + tz + j;
      if (z >= Z_N) continue;
      float prx = pr[i][j], pix = pim[i][j], qrx = qr[i][j], qix = qim[i][j];
      float ipp = 1.f / fmaf(prx, prx, pix * pix);
      float iqq = 1.f / fmaf(qrx, qrx, qix * qix);
      float sre = fmaf(prx, qrx, pix * qix);
      float sim = fmaf(pix, qrx, -prx * qix);
      float f = ipp * iqq;
      int o = a * Z_N + z;
      g_den[0 * PL + o] = ipp;
      g_den[1 * PL + o] = iqq;
      g_den[2 * PL + o] = sre * f;
      g_den[3 * PL + o] = -sim * f;
    }
  }
}

// ---------------- main loss: loop d, GEMM u_d, v_d, fuse epilogue ----------------
__global__ __launch_bounds__(256) void loss_kernel(const float* __restrict__ gammaMN,
                                                   const float* __restrict__ Mmat,
                                                   const float* __restrict__ Xmat) {
  __shared__ float sE1c[16][64];
  __shared__ float sE1s[16][64];
  __shared__ float sE2c[16][64];
  __shared__ float sE2s[16][64];
  __shared__ float sW1[16][64];
  __shared__ float sW2[16][64];
  __shared__ float red[256];
  int tid = threadIdx.x;
  int ablk = blockIdx.y * 64;
  int zblk = blockIdx.x * 64;
  int ta = (tid / 16) * 4;
  int tz = (tid % 16) * 4;
  int e_ar = tid >> 2;
  int e_kc = (tid & 3) * 4;
  int g_kr = tid >> 4;
  int g_zc = (tid & 15) * 4;
  int ga = ablk + e_ar;
  bool a_ok = (ga < A_N);
  int gz = zblk + g_zc;
  bool z_ok = (gz < Z_N);
  const float4 zf4 = make_float4(0.f, 0.f, 0.f, 0.f);
  const int PL = A_N * Z_N;
  float lsum = 0.f;

  for (int d = 0; d < D_N; d++) {
    float ur[4][4], ui[4][4], vr[4][4], vi[4][4];
#pragma unroll
    for (int i = 0; i < 4; i++)
#pragma unroll
      for (int j = 0; j < 4; j++) { ur[i][j] = 0.f; ui[i][j] = 0.f; vr[i][j] = 0.f; vi[i][j] = 0.f; }

    for (int k0 = 0; k0 < N_N; k0 += 16) {
      int eoff = ga * N_N + k0 + e_kc;
      float4 t;
      t = a_ok ? *reinterpret_cast<const float4*>(&g_E1c[eoff]) : zf4;
      sE1c[e_kc + 0][e_ar] = t.x; sE1c[e_kc + 1][e_ar] = t.y; sE1c[e_kc + 2][e_ar] = t.z; sE1c[e_kc + 3][e_ar] = t.w;
      t = a_ok ? *reinterpret_cast<const float4*>(&g_E1s[eoff]) : zf4;
      sE1s[e_kc + 0][e_ar] = t.x; sE1s[e_kc + 1][e_ar] = t.y; sE1s[e_kc + 2][e_ar] = t.z; sE1s[e_kc + 3][e_ar] = t.w;
      t = a_ok ? *reinterpret_cast<const float4*>(&g_E2c[eoff]) : zf4;
      sE2c[e_kc + 0][e_ar] = t.x; sE2c[e_kc + 1][e_ar] = t.y; sE2c[e_kc + 2][e_ar] = t.z; sE2c[e_kc + 3][e_ar] = t.w;
      t = a_ok ? *reinterpret_cast<const float4*>(&g_E2s[eoff]) : zf4;
      sE2s[e_kc + 0][e_ar] = t.x; sE2s[e_kc + 1][e_ar] = t.y; sE2s[e_kc + 2][e_ar] = t.z; sE2s[e_kc + 3][e_ar] = t.w;

      int jg = k0 + g_kr;
      float m_d = Mmat[jg * D_N + d];
      float x_d = Xmat[jg * D_N + d];
      int goff = jg * Z_N + gz;
      float4 gmn = z_ok ? *reinterpret_cast<const float4*>(&gammaMN[goff]) : zf4;
      float4 gxx = z_ok ? *reinterpret_cast<const float4*>(&g_gX[goff]) : zf4;
      float4 w1 = make_float4(gmn.x * m_d, gmn.y * m_d, gmn.z * m_d, gmn.w * m_d);
      float4 w2 = make_float4(gxx.x * x_d, gxx.y * x_d, gxx.z * x_d, gxx.w * x_d);
      *reinterpret_cast<float4*>(&sW1[g_kr][g_zc]) = w1;
      *reinterpret_cast<float4*>(&sW2[g_kr][g_zc]) = w2;
      __syncthreads();

#pragma unroll
      for (int kk = 0; kk < 16; kk++) {
        float e1c[4], e1s[4], e2c[4], e2s[4], wa[4], wb[4];
        LD4(e1c, &sE1c[kk][ta]);
        LD4(e1s, &sE1s[kk][ta]);
        LD4(e2c, &sE2c[kk][ta]);
        LD4(e2s, &sE2s[kk][ta]);
        LD4(wa, &sW1[kk][tz]);
        LD4(wb, &sW2[kk][tz]);
#pragma unroll
        for (int i = 0; i < 4; i++)
#pragma unroll
          for (int j = 0; j < 4; j++) {
            ur[i][j] = fmaf(e1c[i], wa[j], ur[i][j]);
            ui[i][j] = fmaf(e1s[i], wa[j], ui[i][j]);
            vr[i][j] = fmaf(e2c[i], wb[j], vr[i][j]);
            vi[i][j] = fmaf(e2s[i], wb[j], vi[i][j]);
          }
      }
      __syncthreads();
    }

    // per-d epilogue: |u/p - v/q|^2 contribution via precomputed denominator planes
#pragma unroll
    for (int i = 0; i < 4; i++) {
      int a = ablk + ta + i;
      if (a >= A_N) continue;
#pragma unroll
      for (int j = 0; j < 4; j++) {
        int z = zblk + tz + j;
        if (z >= Z_N) continue;
        int o = a * Z_N + z;
        float ipp = g_den[0 * PL + o];
        float iqq = g_den[1 * PL + o];
        float rre = g_den[2 * PL + o];
        float rim = g_den[3 * PL + o];
        float a0 = ur[i][j], b0 = ui[i][j], c0 = vr[i][j], d0 = vi[i][j];
        float uu = fmaf(a0, a0, b0 * b0);
        float vv = fmaf(c0, c0, d0 * d0);
        float xr = fmaf(a0, c0, b0 * d0);
        float xi = fmaf(b0, c0, -a0 * d0);
        lsum += fmaf(uu, ipp, vv * iqq) - 2.f * fmaf(xr, rre, -xi * rim);
      }
    }
  }

  red[tid] = lsum;
  __syncthreads();
  for (int s = 128; s > 0; s >>= 1) {
    if (tid < s) red[tid] += red[tid + s];
    __syncthreads();
  }
  if (tid == 0) atomicAdd(&g_acc, red[0]);
}

__global__ void finalize_kernel(float* out) {
  out[0] = g_acc * (1.f / (float)(A_N * Z_N));
}

// ---------------- launch ----------------
extern "C" void kernel_launch(void* const* d_in, const int* in_sizes, int n_in,
                              void* d_out, int out_size) {
  const float* Mmat  = (const float*)d_in[0];
  const float* Nmat  = (const float*)d_in[1];
  const float* Xmat  = (const float*)d_in[2];
  const float* llam  = (const float*)d_in[3];
  const float* Kz    = (const float*)d_in[4];
  const float* Bz    = (const float*)d_in[5];
  const float* gMN   = (const float*)d_in[6];
  const float* gN    = (const float*)d_in[7];
  const float* alpha = (const float*)d_in[8];
  float* out = (float*)d_out;

  float *pT1, *pT2;
  cudaGetSymbolAddress((void**)&pT1, g_T1);
  cudaGetSymbolAddress((void**)&pT2, g_T2);

  zero_acc_kernel<<<1, 1>>>();
  trig_kernel<<<(A_N * N_N + 255) / 256, 256>>>(alpha, Nmat, Xmat);

  dim3 gg((Z_N + 127) / 128, (N_N + 127) / 128);
  sgemm2000<<<gg, 256>>>(Kz, Bz, pT1);
  sgemm2000<<<gg, 256>>>(Kz, pT1, pT2);
  combine_gamma_kernel<<<(N_N * Z_N + 255) / 256, 256>>>(Bz, llam);

  dim3 gd((Z_N + 63) / 64, (A_N + 63) / 64);
  denom_kernel<<<gd, 256>>>(gN);
  loss_kernel<<<gd, 256>>>(gMN, Mmat, Xmat);
  finalize_kernel<<<1, 1>>>(out);
}

// round 7
// speedup vs baseline: 5.1200x; 5.1200x over previous
#include <cuda_runtime.h>
#include <cuda_bf16.h>
#include <cstdint>
#include <math.h>

#define A_N 1000
#define N_N 2000
#define Z_N 2000
#define D_N 8
#define GK  2048   // padded square dimension for all GEMMs
#define LDA 72     // smem row stride (elems) for GEMM tiles

// ---------------- device scratch (no cudaMalloc allowed) ----------------
__device__ __nv_bfloat16 g_Kbf [GK * GK];  // K_Z1Z1 bf16 padded
__device__ __nv_bfloat16 g_Bzt [GK * GK];  // K_Z1Z2^T bf16
__device__ __nv_bfloat16 g_gNt [GK * GK];  // gamma_N^T hi
__device__ __nv_bfloat16 g_gNlo[GK * GK];  // gamma_N^T lo
__device__ __nv_bfloat16 g_gMNt[GK * GK];  // gamma_MN^T hi
__device__ __nv_bfloat16 g_gXt [GK * GK];  // gamma_X^T hi
__device__ __nv_bfloat16 g_gXlo[GK * GK];  // gamma_X^T lo
__device__ __nv_bfloat16 g_E1st[GK * GK];  // stacked E1 (rows 0-999 cos, 1024-2023 sin) hi
__device__ __nv_bfloat16 g_E1lo[GK * GK];
__device__ __nv_bfloat16 g_E2st[GK * GK];
__device__ __nv_bfloat16 g_E2lo[GK * GK];
__device__ __nv_bfloat16 g_W1t [GK * GK];  // weighted gamma for numerators
__device__ __nv_bfloat16 g_W2t [GK * GK];
__device__ float  g_C1[GK * GK];           // T1 -> P -> U   (C[m][n] fp32)
__device__ float  g_C2[GK * GK];           // Q -> V
__device__ float4 g_den4[A_N * Z_N];       // [a][z]: {1/|p|^2, 1/|q|^2, rre, rim}
__device__ float  g_acc;

// ---------------- mma helpers (portable PTX: sm_80+, valid at compute_103) ----------------
__device__ __forceinline__ uint32_t smem_u32(const void* p) {
  uint32_t a;
  asm("{ .reg .u64 t; cvta.to.shared.u64 t, %1; cvt.u32.u64 %0, t; }" : "=r"(a) : "l"(p));
  return a;
}
__device__ __forceinline__ void ldsm4(uint32_t* r, uint32_t addr) {
  asm volatile("ldmatrix.sync.aligned.m8n8.x4.shared.b16 {%0,%1,%2,%3}, [%4];"
               : "=r"(r[0]), "=r"(r[1]), "=r"(r[2]), "=r"(r[3]) : "r"(addr));
}
__device__ __forceinline__ void mma16816(float* c, const uint32_t* a, const uint32_t* b) {
  asm volatile(
      "mma.sync.aligned.m16n8k16.row.col.f32.bf16.bf16.f32 "
      "{%0,%1,%2,%3}, {%4,%5,%6,%7}, {%8,%9}, {%0,%1,%2,%3};"
      : "+f"(c[0]), "+f"(c[1]), "+f"(c[2]), "+f"(c[3])
      : "r"(a[0]), "r"(a[1]), "r"(a[2]), "r"(a[3]), "r"(b[0]), "r"(b[1]));
}
__device__ __forceinline__ void wr_hilo(__nv_bfloat16* hi, __nv_bfloat16* lo,
                                        size_t o, float v) {
  __nv_bfloat16 h = __float2bfloat16(v);
  hi[o] = h;
  lo[o] = __float2bfloat16(v - __bfloat162float(h));
}

// ---------------- small kernels ----------------
__global__ void zero_acc_kernel() { g_acc = 0.f; }

// phase features, plane-stacked, hi/lo split
__global__ void trig_kernel(const float* __restrict__ alpha,
                            const float* __restrict__ Nmat,
                            const float* __restrict__ Xmat) {
  int idx = blockIdx.x * blockDim.x + threadIdx.x;   // a*2048 + j
  if (idx >= A_N * GK) return;
  int a = idx >> 11;
  int j = idx & (GK - 1);
  size_t oA = (size_t)a * GK + j;
  size_t oB = (size_t)(1024 + a) * GK + j;
  if (j >= N_N) {
    __nv_bfloat16 z = __float2bfloat16(0.f);
    g_E1st[oA] = z; g_E1st[oB] = z; g_E1lo[oA] = z; g_E1lo[oB] = z;
    g_E2st[oA] = z; g_E2st[oB] = z; g_E2lo[oA] = z; g_E2lo[oB] = z;
    return;
  }
  float ph1 = 0.f, ph2 = 0.f;
#pragma unroll
  for (int d = 0; d < D_N; d++) {
    float al = alpha[a * D_N + d];
    ph1 = fmaf(al, Nmat[j * D_N + d], ph1);
    ph2 = fmaf(al, Xmat[j * D_N + d], ph2);
  }
  float s1, c1, s2, c2;
  sincosf(ph1, &s1, &c1);
  sincosf(ph2, &s2, &c2);
  wr_hilo(g_E1st, g_E1lo, oA, c1);
  wr_hilo(g_E1st, g_E1lo, oB, s1);
  wr_hilo(g_E2st, g_E2lo, oA, c2);
  wr_hilo(g_E2st, g_E2lo, oB, s2);
}

// zero pad rows (1000-1023, 2024-2047) of the E stacks
__global__ void pad_rows_kernel() {
  int idx = blockIdx.x * blockDim.x + threadIdx.x;   // 48*2048
  if (idx >= 48 * GK) return;
  int row = idx >> 11;
  int col = idx & (GK - 1);
  int m = (row < 24) ? (1000 + row) : (2024 + (row - 24));
  size_t o = (size_t)m * GK + col;
  __nv_bfloat16 z = __float2bfloat16(0.f);
  g_E1st[o] = z; g_E1lo[o] = z; g_E2st[o] = z; g_E2lo[o] = z;
}

// K_Z1Z1 fp32[2000x2000] -> bf16 [2048x2048] padded
__global__ void cvt_pad_kernel(const float* __restrict__ K) {
  int idx = blockIdx.x * blockDim.x + threadIdx.x;
  if (idx >= GK * GK) return;
  int i = idx >> 11;
  int j = idx & (GK - 1);
  float v = (i < N_N && j < Z_N) ? K[(size_t)i * Z_N + j] : 0.f;
  g_Kbf[idx] = __float2bfloat16(v);
}

// transpose fp32 [2000(n) x 2000(z)] -> bf16 [2048(z) x 2048(n)], optional lo plane
__global__ void transpose_cvt_kernel(const float* __restrict__ in,
                                     __nv_bfloat16* __restrict__ outHi,
                                     __nv_bfloat16* __restrict__ outLo,
                                     int withLo) {
  __shared__ float t[32][33];
  int n0 = blockIdx.x * 32, z0 = blockIdx.y * 32;
  int tx = threadIdx.x, ty = threadIdx.y;
#pragma unroll
  for (int dy = 0; dy < 4; dy++) {
    int n = n0 + ty + dy * 8, z = z0 + tx;
    t[ty + dy * 8][tx] = (n < N_N && z < Z_N) ? in[(size_t)n * Z_N + z] : 0.f;
  }
  __syncthreads();
#pragma unroll
  for (int dy = 0; dy < 4; dy++) {
    int z = z0 + ty + dy * 8, n = n0 + tx;
    float v = t[tx][ty + dy * 8];
    size_t o = (size_t)z * GK + n;
    __nv_bfloat16 h = __float2bfloat16(v);
    outHi[o] = h;
    if (withLo) outLo[o] = __float2bfloat16(v - __bfloat162float(h));
  }
}

// ---------------- mma.sync bf16 GEMM ----------------
// C[m][n] = sum_pairs A_p[m][k] * B_p[n][k]; CTA tile 128x128, kchunk 64.
__global__ __launch_bounds__(256) void gemm_mma(
    const __nv_bfloat16* __restrict__ A0, const __nv_bfloat16* __restrict__ B0,
    const __nv_bfloat16* __restrict__ A1, const __nv_bfloat16* __restrict__ B1,
    const __nv_bfloat16* __restrict__ A2, const __nv_bfloat16* __restrict__ B2,
    int npairs, float* __restrict__ C) {
  __shared__ __nv_bfloat16 As[128 * LDA];
  __shared__ __nv_bfloat16 Bs[128 * LDA];
  int tid = threadIdx.x, lane = tid & 31, wid = tid >> 5;
  int wm = wid & 3, wn = wid >> 2;           // 4 m-warps x 2 n-warps
  int mblk = blockIdx.y * 128, nblk = blockIdx.x * 128;

  float c[2][8][4];
#pragma unroll
  for (int i = 0; i < 2; i++)
#pragma unroll
    for (int j = 0; j < 8; j++)
#pragma unroll
      for (int e = 0; e < 4; e++) c[i][j][e] = 0.f;

  int srow = tid >> 3;            // 0..31
  int scol = (tid & 7) * 8;       // 0..56

  uint32_t asb = smem_u32(As), bsb = smem_u32(Bs);
  // A frag addresses: mats (m0-7,k0),(m8-15,k0),(m0-7,k8),(m8-15,k8)
  uint32_t aAddr = asb + (uint32_t)(((wm * 32 + (lane & 15)) * LDA + ((lane >> 4) * 8)) * 2);
  // B frag addresses: mats (n0-7,k0),(n0-7,k8),(n8-15,k0),(n8-15,k8)
  uint32_t bAddr = bsb + (uint32_t)(((wn * 64 + ((lane >> 4) << 3) + (lane & 7)) * LDA +
                                     (((lane >> 3) & 1) * 8)) * 2);

  int nch = npairs * 32;
  uint4 pa[4], pb[4];
  // prologue: load chunk 0
#pragma unroll
  for (int p = 0; p < 4; p++) {
    int row = p * 32 + srow;
    pa[p] = *reinterpret_cast<const uint4*>(A0 + (size_t)(mblk + row) * GK + scol);
    pb[p] = *reinterpret_cast<const uint4*>(B0 + (size_t)(nblk + row) * GK + scol);
  }

  for (int ch = 0; ch < nch; ch++) {
#pragma unroll
    for (int p = 0; p < 4; p++) {
      int row = p * 32 + srow;
      *reinterpret_cast<uint4*>(As + row * LDA + scol) = pa[p];
      *reinterpret_cast<uint4*>(Bs + row * LDA + scol) = pb[p];
    }
    __syncthreads();
    if (ch + 1 < nch) {
      int pr = (ch + 1) >> 5;
      const __nv_bfloat16* Ap = (pr == 0) ? A0 : (pr == 1) ? A1 : A2;
      const __nv_bfloat16* Bp = (pr == 0) ? B0 : (pr == 1) ? B1 : B2;
      int k0 = ((ch + 1) & 31) * 64;
#pragma unroll
      for (int p = 0; p < 4; p++) {
        int row = p * 32 + srow;
        pa[p] = *reinterpret_cast<const uint4*>(Ap + (size_t)(mblk + row) * GK + k0 + scol);
        pb[p] = *reinterpret_cast<const uint4*>(Bp + (size_t)(nblk + row) * GK + k0 + scol);
      }
    }
#pragma unroll
    for (int ks = 0; ks < 4; ks++) {
      uint32_t af0[4], af1[4];
      ldsm4(af0, aAddr + ks * 32);
      ldsm4(af1, aAddr + 16 * LDA * 2 + ks * 32);
#pragma unroll
      for (int j2 = 0; j2 < 4; j2++) {
        uint32_t bf4[4];
        ldsm4(bf4, bAddr + j2 * (16 * LDA * 2) + ks * 32);
        mma16816(c[0][j2 * 2],     af0, bf4);
        mma16816(c[0][j2 * 2 + 1], af0, bf4 + 2);
        mma16816(c[1][j2 * 2],     af1, bf4);
        mma16816(c[1][j2 * 2 + 1], af1, bf4 + 2);
      }
    }
    __syncthreads();
  }

  // epilogue: coalesced float2 stores, C[m][n]
  int r0 = mblk + wm * 32 + (lane >> 2);
  int c0 = nblk + wn * 64 + (lane & 3) * 2;
#pragma unroll
  for (int i = 0; i < 2; i++)
#pragma unroll
    for (int j = 0; j < 8; j++) {
      int row = r0 + i * 16;
      int col = c0 + j * 8;
      *reinterpret_cast<float2*>(&C[(size_t)row * GK + col]) =
          make_float2(c[i][j][0], c[i][j][1]);
      *reinterpret_cast<float2*>(&C[(size_t)(row + 8) * GK + col]) =
          make_float2(c[i][j][2], c[i][j][3]);
    }
}

// gamma_X^T: reads Bz[k][z] fp32 and T1=g_C1[k][z], writes gXt[z][k] hi+lo (transposed)
__global__ void combine_t_kernel(const float* __restrict__ B,
                                 const float* __restrict__ loglam) {
  __shared__ float t[32][33];
  float ic = 1.f / ((float)N_N * expf(loglam[0]));
  int k0 = blockIdx.x * 32, z0 = blockIdx.y * 32;
  int tx = threadIdx.x, ty = threadIdx.y;
#pragma unroll
  for (int dy = 0; dy < 4; dy++) {
    int k = k0 + ty + dy * 8, z = z0 + tx;
    float v = 0.f;
    if (k < N_N && z < Z_N)
      v = (B[(size_t)k * Z_N + z] - g_C1[(size_t)k * GK + z] * ic) * ic;
    t[ty + dy * 8][tx] = v;
  }
  __syncthreads();
#pragma unroll
  for (int dy = 0; dy < 4; dy++) {
    int z = z0 + ty + dy * 8, k = k0 + tx;
    size_t o = (size_t)z * GK + k;
    wr_hilo(g_gXt, g_gXlo, o, t[tx][ty + dy * 8]);
  }
}

// Wt[z][k] = bf16(Gt[z][k] * MX[k][d])
__global__ void prepW_kernel(const __nv_bfloat16* __restrict__ Gt,
                             const float* __restrict__ MX, int d,
                             __nv_bfloat16* __restrict__ Wt) {
  int idx8 = blockIdx.x * blockDim.x + threadIdx.x;  // 2048*256
  if (idx8 >= GK * (GK / 8)) return;
  int z = idx8 >> 8;
  int k8 = (idx8 & 255) << 3;
  uint4 gv = *reinterpret_cast<const uint4*>(Gt + (size_t)z * GK + k8);
  const __nv_bfloat16* gp = reinterpret_cast<const __nv_bfloat16*>(&gv);
  uint4 ov;
  __nv_bfloat16* op = reinterpret_cast<__nv_bfloat16*>(&ov);
#pragma unroll
  for (int e = 0; e < 8; e++) {
    int k = k8 + e;
    float md = (k < N_N) ? MX[k * D_N + d] : 0.f;
    op[e] = __float2bfloat16(__bfloat162float(gp[e]) * md);
  }
  *reinterpret_cast<uint4*>(Wt + (size_t)z * GK + k8) = ov;
}

// denominator planes from P (g_C1), Q (g_C2); grid (8, A_N)
__global__ void den4_kernel() {
  int z = blockIdx.x * blockDim.x + threadIdx.x;
  int a = blockIdx.y;
  if (z >= Z_N) return;
  float pr = g_C1[(size_t)a * GK + z],          pi = g_C1[(size_t)(1024 + a) * GK + z];
  float qr = g_C2[(size_t)a * GK + z],          qi = g_C2[(size_t)(1024 + a) * GK + z];
  float ipp = 1.f / fmaf(pr, pr, pi * pi);
  float iqq = 1.f / fmaf(qr, qr, qi * qi);
  float sre = fmaf(pr, qr, pi * qi);
  float sim = fmaf(pi, qr, -pr * qi);
  float f = ipp * iqq;
  g_den4[(size_t)a * Z_N + z] = make_float4(ipp, iqq, sre * f, -sim * f);
}

// per-d loss accumulation from U (g_C1), V (g_C2); grid (8, A_N)
__global__ __launch_bounds__(256) void loss_epi_kernel() {
  __shared__ float red[256];
  int tid = threadIdx.x;
  int z = blockIdx.x * blockDim.x + tid;
  int a = blockIdx.y;
  float lsum = 0.f;
  if (z < Z_N) {
    float ur = g_C1[(size_t)a * GK + z],        ui = g_C1[(size_t)(1024 + a) * GK + z];
    float vr = g_C2[(size_t)a * GK + z],        vi = g_C2[(size_t)(1024 + a) * GK + z];
    float4 dn = g_den4[(size_t)a * Z_N + z];
    float uu = fmaf(ur, ur, ui * ui);
    float vv = fmaf(vr, vr, vi * vi);
    float xr = fmaf(ur, vr, ui * vi);
    float xi = fmaf(ui, vr, -ur * vi);
    lsum = fmaf(uu, dn.x, vv * dn.y) - 2.f * fmaf(xr, dn.z, -xi * dn.w);
  }
  red[tid] = lsum;
  __syncthreads();
  for (int s = 128; s > 0; s >>= 1) {
    if (tid < s) red[tid] += red[tid + s];
    __syncthreads();
  }
  if (tid == 0) atomicAdd(&g_acc, red[0]);
}

__global__ void finalize_kernel(float* out) {
  out[0] = g_acc * (1.f / (float)(A_N * Z_N));
}

// ---------------- launch ----------------
extern "C" void kernel_launch(void* const* d_in, const int* in_sizes, int n_in,
                              void* d_out, int out_size) {
  const float* Mmat  = (const float*)d_in[0];
  const float* Nmat  = (const float*)d_in[1];
  const float* Xmat  = (const float*)d_in[2];
  const float* llam  = (const float*)d_in[3];
  const float* Kz    = (const float*)d_in[4];
  const float* Bz    = (const float*)d_in[5];
  const float* gMN   = (const float*)d_in[6];
  const float* gN    = (const float*)d_in[7];
  const float* alpha = (const float*)d_in[8];
  float* out = (float*)d_out;

  __nv_bfloat16 *pKbf, *pBzt, *pgNt, *pgNlo, *pgMNt, *pgXt, *pgXlo;
  __nv_bfloat16 *pE1, *pE1lo, *pE2, *pE2lo, *pW1, *pW2;
  float *pC1, *pC2;
  cudaGetSymbolAddress((void**)&pKbf,  g_Kbf);
  cudaGetSymbolAddress((void**)&pBzt,  g_Bzt);
  cudaGetSymbolAddress((void**)&pgNt,  g_gNt);
  cudaGetSymbolAddress((void**)&pgNlo, g_gNlo);
  cudaGetSymbolAddress((void**)&pgMNt, g_gMNt);
  cudaGetSymbolAddress((void**)&pgXt,  g_gXt);
  cudaGetSymbolAddress((void**)&pgXlo, g_gXlo);
  cudaGetSymbolAddress((void**)&pE1,   g_E1st);
  cudaGetSymbolAddress((void**)&pE1lo, g_E1lo);
  cudaGetSymbolAddress((void**)&pE2,   g_E2st);
  cudaGetSymbolAddress((void**)&pE2lo, g_E2lo);
  cudaGetSymbolAddress((void**)&pW1,   g_W1t);
  cudaGetSymbolAddress((void**)&pW2,   g_W2t);
  cudaGetSymbolAddress((void**)&pC1,   g_C1);
  cudaGetSymbolAddress((void**)&pC2,   g_C2);

  dim3 t32(32, 8);
  dim3 g64(64, 64);
  dim3 gg(16, 16);          // GEMM grid: 16 n-tiles x 16 m-tiles (128x128 tiles)
  dim3 gel(8, A_N);         // elementwise (z, a) grids

  zero_acc_kernel<<<1, 1>>>();
  trig_kernel<<<(A_N * GK) / 256, 256>>>(alpha, Nmat, Xmat);
  pad_rows_kernel<<<(48 * GK) / 256, 256>>>();
  cvt_pad_kernel<<<(GK * GK) / 256, 256>>>(Kz);
  transpose_cvt_kernel<<<g64, t32>>>(Bz, pBzt, pBzt, 0);
  transpose_cvt_kernel<<<g64, t32>>>(gN, pgNt, pgNlo, 1);
  transpose_cvt_kernel<<<g64, t32>>>(gMN, pgMNt, pgMNt, 0);

  // Neumann (1 term): T1[i][z] = (K @ B)[i][z]
  gemm_mma<<<gg, 256>>>(pKbf, pBzt, pKbf, pBzt, pKbf, pBzt, 1, pC1);
  combine_t_kernel<<<g64, t32>>>(Bz, llam);

  // denominators with split-bf16 3-pair accumulation
  gemm_mma<<<gg, 256>>>(pE1, pgNt, pE1, pgNlo, pE1lo, pgNt, 3, pC1);
  gemm_mma<<<gg, 256>>>(pE2, pgXt, pE2, pgXlo, pE2lo, pgXt, 3, pC2);
  den4_kernel<<<gel, 256>>>();

  // per-d numerators + fused loss epilogue
  for (int d = 0; d < D_N; d++) {
    prepW_kernel<<<(GK * GK / 8) / 256, 256>>>(pgMNt, Mmat, d, pW1);
    gemm_mma<<<gg, 256>>>(pE1, pW1, pE1, pW1, pE1, pW1, 1, pC1);
    prepW_kernel<<<(GK * GK / 8) / 256, 256>>>(pgXt, Xmat, d, pW2);
    gemm_mma<<<gg, 256>>>(pE2, pW2, pE2, pW2, pE2, pW2, 1, pC2);
    loss_epi_kernel<<<gel, 256>>>();
  }
  finalize_kernel<<<1, 1>>>(out);
}

// round 8
// speedup vs baseline: 5.8584x; 1.1442x over previous
#include <cuda_runtime.h>
#include <cuda_bf16.h>
#include <cstdint>
#include <math.h>

#define A_N 1000
#define N_N 2000
#define Z_N 2000
#define D_N 8
#define GK  2048   // padded square dimension for all GEMMs
#define LDA 72     // smem row stride (elems) for GEMM tiles
#define STAGE_BYTES 36864           // (128 A rows + 128 B rows) * 144 B
#define B_OFF 18432                 // B tile offset within a stage
#define NSTAGE 3
#define SMEM_GEMM (NSTAGE * STAGE_BYTES)

// ---------------- device scratch (no cudaMalloc allowed) ----------------
__device__ __nv_bfloat16 g_Kbf [GK * GK];      // K_Z1Z1 bf16 padded
__device__ __nv_bfloat16 g_Bzt [GK * GK];      // K_Z1Z2^T bf16
__device__ __nv_bfloat16 g_gNt [GK * GK];      // gamma_N^T hi
__device__ __nv_bfloat16 g_gNlo[GK * GK];      // gamma_N^T lo
__device__ __nv_bfloat16 g_gMNt[GK * GK];      // gamma_MN^T hi
__device__ __nv_bfloat16 g_gXt [GK * GK];      // gamma_X^T hi
__device__ __nv_bfloat16 g_gXlo[GK * GK];      // gamma_X^T lo
__device__ __nv_bfloat16 g_E1st[GK * GK];      // stacked E1 (rows 0-999 cos, 1024-2023 sin) hi
__device__ __nv_bfloat16 g_E1lo[GK * GK];
__device__ __nv_bfloat16 g_E2st[GK * GK];
__device__ __nv_bfloat16 g_E2lo[GK * GK];
__device__ __nv_bfloat16 g_W1t [8 * GK * GK];  // all-d weighted gamma, rows (d*2048+z)
__device__ __nv_bfloat16 g_W2t [8 * GK * GK];
__device__ float  g_C1[8 * GK * GK];           // T1/P (ldc 2048) or U_all (ldc 16384)
__device__ float  g_C2[8 * GK * GK];           // Q (ldc 2048) or V_all (ldc 16384)
__device__ float4 g_den4[A_N * Z_N];           // [a][z]: {1/|p|^2, 1/|q|^2, rre, rim}
__device__ float  g_acc;

// ---------------- mma / cp.async helpers (portable PTX, valid at compute_103) ----------------
__device__ __forceinline__ uint32_t smem_u32(const void* p) {
  uint32_t a;
  asm("{ .reg .u64 t; cvta.to.shared.u64 t, %1; cvt.u32.u64 %0, t; }" : "=r"(a) : "l"(p));
  return a;
}
__device__ __forceinline__ void ldsm4(uint32_t* r, uint32_t addr) {
  asm volatile("ldmatrix.sync.aligned.m8n8.x4.shared.b16 {%0,%1,%2,%3}, [%4];"
               : "=r"(r[0]), "=r"(r[1]), "=r"(r[2]), "=r"(r[3]) : "r"(addr));
}
__device__ __forceinline__ void mma16816(float* c, const uint32_t* a, const uint32_t* b) {
  asm volatile(
      "mma.sync.aligned.m16n8k16.row.col.f32.bf16.bf16.f32 "
      "{%0,%1,%2,%3}, {%4,%5,%6,%7}, {%8,%9}, {%0,%1,%2,%3};"
      : "+f"(c[0]), "+f"(c[1]), "+f"(c[2]), "+f"(c[3])
      : "r"(a[0]), "r"(a[1]), "r"(a[2]), "r"(a[3]), "r"(b[0]), "r"(b[1]));
}
#define CP_ASYNC16(dst, src) \
  asm volatile("cp.async.cg.shared.global [%0], [%1], 16;" :: "r"(dst), "l"(src))
#define CP_COMMIT() asm volatile("cp.async.commit_group;" ::: "memory")
#define CP_WAIT1()  asm volatile("cp.async.wait_group 1;" ::: "memory")

__device__ __forceinline__ void wr_hilo(__nv_bfloat16* hi, __nv_bfloat16* lo,
                                        size_t o, float v) {
  __nv_bfloat16 h = __float2bfloat16(v);
  hi[o] = h;
  lo[o] = __float2bfloat16(v - __bfloat162float(h));
}

// ---------------- small kernels ----------------
__global__ void zero_acc_kernel() { g_acc = 0.f; }

// phase features, plane-stacked, hi/lo split
__global__ void trig_kernel(const float* __restrict__ alpha,
                            const float* __restrict__ Nmat,
                            const float* __restrict__ Xmat) {
  int idx = blockIdx.x * blockDim.x + threadIdx.x;   // a*2048 + j
  if (idx >= A_N * GK) return;
  int a = idx >> 11;
  int j = idx & (GK - 1);
  size_t oA = (size_t)a * GK + j;
  size_t oB = (size_t)(1024 + a) * GK + j;
  if (j >= N_N) {
    __nv_bfloat16 z = __float2bfloat16(0.f);
    g_E1st[oA] = z; g_E1st[oB] = z; g_E1lo[oA] = z; g_E1lo[oB] = z;
    g_E2st[oA] = z; g_E2st[oB] = z; g_E2lo[oA] = z; g_E2lo[oB] = z;
    return;
  }
  float ph1 = 0.f, ph2 = 0.f;
#pragma unroll
  for (int d = 0; d < D_N; d++) {
    float al = alpha[a * D_N + d];
    ph1 = fmaf(al, Nmat[j * D_N + d], ph1);
    ph2 = fmaf(al, Xmat[j * D_N + d], ph2);
  }
  float s1, c1, s2, c2;
  sincosf(ph1, &s1, &c1);
  sincosf(ph2, &s2, &c2);
  wr_hilo(g_E1st, g_E1lo, oA, c1);
  wr_hilo(g_E1st, g_E1lo, oB, s1);
  wr_hilo(g_E2st, g_E2lo, oA, c2);
  wr_hilo(g_E2st, g_E2lo, oB, s2);
}

// zero pad rows (1000-1023, 2024-2047) of the E stacks
__global__ void pad_rows_kernel() {
  int idx = blockIdx.x * blockDim.x + threadIdx.x;   // 48*2048
  if (idx >= 48 * GK) return;
  int row = idx >> 11;
  int col = idx & (GK - 1);
  int m = (row < 24) ? (1000 + row) : (2024 + (row - 24));
  size_t o = (size_t)m * GK + col;
  __nv_bfloat16 z = __float2bfloat16(0.f);
  g_E1st[o] = z; g_E1lo[o] = z; g_E2st[o] = z; g_E2lo[o] = z;
}

// K_Z1Z1 fp32[2000x2000] -> bf16 [2048x2048] padded
__global__ void cvt_pad_kernel(const float* __restrict__ K) {
  int idx = blockIdx.x * blockDim.x + threadIdx.x;
  if (idx >= GK * GK) return;
  int i = idx >> 11;
  int j = idx & (GK - 1);
  float v = (i < N_N && j < Z_N) ? K[(size_t)i * Z_N + j] : 0.f;
  g_Kbf[idx] = __float2bfloat16(v);
}

// transpose fp32 [2000(n) x 2000(z)] -> bf16 [2048(z) x 2048(n)], optional lo plane
__global__ void transpose_cvt_kernel(const float* __restrict__ in,
                                     __nv_bfloat16* __restrict__ outHi,
                                     __nv_bfloat16* __restrict__ outLo,
                                     int withLo) {
  __shared__ float t[32][33];
  int n0 = blockIdx.x * 32, z0 = blockIdx.y * 32;
  int tx = threadIdx.x, ty = threadIdx.y;
#pragma unroll
  for (int dy = 0; dy < 4; dy++) {
    int n = n0 + ty + dy * 8, z = z0 + tx;
    t[ty + dy * 8][tx] = (n < N_N && z < Z_N) ? in[(size_t)n * Z_N + z] : 0.f;
  }
  __syncthreads();
#pragma unroll
  for (int dy = 0; dy < 4; dy++) {
    int z = z0 + ty + dy * 8, n = n0 + tx;
    float v = t[tx][ty + dy * 8];
    size_t o = (size_t)z * GK + n;
    __nv_bfloat16 h = __float2bfloat16(v);
    outHi[o] = h;
    if (withLo) outLo[o] = __float2bfloat16(v - __bfloat162float(h));
  }
}

// ---------------- cp.async 3-stage pipelined mma.sync bf16 GEMM ----------------
// C[m][n] = sum_pairs A_p[m][k] * B_p[n][k]; CTA tile 128x128, kchunk 64.
// B may have more than 2048 rows (batched-N); ldc parametrizes C row stride.
__global__ __launch_bounds__(256) void gemm_cp(
    const __nv_bfloat16* __restrict__ A0, const __nv_bfloat16* __restrict__ B0,
    const __nv_bfloat16* __restrict__ A1, const __nv_bfloat16* __restrict__ B1,
    const __nv_bfloat16* __restrict__ A2, const __nv_bfloat16* __restrict__ B2,
    int npairs, float* __restrict__ C, int ldc) {
  extern __shared__ char sm[];
  uint32_t smb = smem_u32(sm);
  int tid = threadIdx.x, lane = tid & 31, wid = tid >> 5;
  int wm = wid & 3, wn = wid >> 2;           // 4 m-warps x 2 n-warps
  int mblk = blockIdx.y * 128, nblk = blockIdx.x * 128;

  float c[2][8][4];
#pragma unroll
  for (int i = 0; i < 2; i++)
#pragma unroll
    for (int j = 0; j < 8; j++)
#pragma unroll
      for (int e = 0; e < 4; e++) c[i][j][e] = 0.f;

  int srow = tid >> 3;            // 0..31
  int scol = (tid & 7) * 8;       // 0..56
  uint32_t sdst = smb + (uint32_t)((srow * LDA + scol) * 2);

  // ldmatrix fragment addresses (same mapping as the passing R7 kernel)
  uint32_t aAddr = smb + (uint32_t)(((wm * 32 + (lane & 15)) * LDA + ((lane >> 4) * 8)) * 2);
  uint32_t bAddr = smb + B_OFF +
                   (uint32_t)(((wn * 64 + ((lane >> 4) << 3) + (lane & 7)) * LDA +
                               (((lane >> 3) & 1) * 8)) * 2);

  int nch = npairs * 32;

#define ISSUE_CHUNK(CH, SLOT)                                                        \
  do {                                                                               \
    int _pr = (CH) >> 5;                                                             \
    const __nv_bfloat16* _Ap = (_pr == 0) ? A0 : (_pr == 1) ? A1 : A2;               \
    const __nv_bfloat16* _Bp = (_pr == 0) ? B0 : (_pr == 1) ? B1 : B2;               \
    int _k0 = ((CH) & 31) * 64;                                                      \
    uint32_t _sb = sdst + (SLOT) * STAGE_BYTES;                                      \
    _Pragma("unroll")                                                                \
    for (int _p = 0; _p < 4; _p++) {                                                 \
      int _row = _p * 32 + srow;                                                     \
      CP_ASYNC16(_sb + _p * (32 * LDA * 2),                                          \
                 _Ap + (size_t)(mblk + _row) * GK + _k0 + scol);                     \
      CP_ASYNC16(_sb + B_OFF + _p * (32 * LDA * 2),                                  \
                 _Bp + (size_t)(nblk + _row) * GK + _k0 + scol);                     \
    }                                                                                \
    CP_COMMIT();                                                                     \
  } while (0)

  ISSUE_CHUNK(0, 0);
  ISSUE_CHUNK(1, 1);

  int slot = 0, nslot = 2;
  for (int ch = 0; ch < nch; ch++) {
    CP_WAIT1();
    __syncthreads();
    uint32_t soff = (uint32_t)slot * STAGE_BYTES;
#pragma unroll
    for (int ks = 0; ks < 4; ks++) {
      uint32_t af0[4], af1[4];
      ldsm4(af0, aAddr + soff + ks * 32);
      ldsm4(af1, aAddr + soff + 16 * LDA * 2 + ks * 32);
#pragma unroll
      for (int j2 = 0; j2 < 4; j2++) {
        uint32_t bf4[4];
        ldsm4(bf4, bAddr + soff + j2 * (16 * LDA * 2) + ks * 32);
        mma16816(c[0][j2 * 2],     af0, bf4);
        mma16816(c[0][j2 * 2 + 1], af0, bf4 + 2);
        mma16816(c[1][j2 * 2],     af1, bf4);
        mma16816(c[1][j2 * 2 + 1], af1, bf4 + 2);
      }
    }
    __syncthreads();
    if (ch + 2 < nch) {
      ISSUE_CHUNK(ch + 2, nslot);
    } else {
      CP_COMMIT();   // keep group counting consistent in the tail
    }
    if (++slot == NSTAGE) slot = 0;
    if (++nslot == NSTAGE) nslot = 0;
  }
#undef ISSUE_CHUNK

  // epilogue: coalesced float2 stores, C[m][n]
  int r0 = mblk + wm * 32 + (lane >> 2);
  int c0 = nblk + wn * 64 + (lane & 3) * 2;
#pragma unroll
  for (int i = 0; i < 2; i++)
#pragma unroll
    for (int j = 0; j < 8; j++) {
      int row = r0 + i * 16;
      int col = c0 + j * 8;
      *reinterpret_cast<float2*>(&C[(size_t)row * ldc + col]) =
          make_float2(c[i][j][0], c[i][j][1]);
      *reinterpret_cast<float2*>(&C[(size_t)(row + 8) * ldc + col]) =
          make_float2(c[i][j][2], c[i][j][3]);
    }
}

// gamma_X^T: reads Bz[k][z] fp32 and T1=g_C1[k][z] (ldc 2048), writes gXt[z][k] hi+lo
__global__ void combine_t_kernel(const float* __restrict__ B,
                                 const float* __restrict__ loglam) {
  __shared__ float t[32][33];
  float ic = 1.f / ((float)N_N * expf(loglam[0]));
  int k0 = blockIdx.x * 32, z0 = blockIdx.y * 32;
  int tx = threadIdx.x, ty = threadIdx.y;
#pragma unroll
  for (int dy = 0; dy < 4; dy++) {
    int k = k0 + ty + dy * 8, z = z0 + tx;
    float v = 0.f;
    if (k < N_N && z < Z_N)
      v = (B[(size_t)k * Z_N + z] - g_C1[(size_t)k * GK + z] * ic) * ic;
    t[ty + dy * 8][tx] = v;
  }
  __syncthreads();
#pragma unroll
  for (int dy = 0; dy < 4; dy++) {
    int z = z0 + ty + dy * 8, k = k0 + tx;
    size_t o = (size_t)z * GK + k;
    wr_hilo(g_gXt, g_gXlo, o, t[tx][ty + dy * 8]);
  }
}

// W[(d*2048+z)][k] = bf16(Gt[z][k] * MX[k][d]) for all 8 d in one pass
__global__ void prepW_all_kernel(const __nv_bfloat16* __restrict__ Gt,
                                 const float* __restrict__ MX,
                                 __nv_bfloat16* __restrict__ W) {
  int idx8 = blockIdx.x * blockDim.x + threadIdx.x;  // 2048 * 256
  if (idx8 >= GK * (GK / 8)) return;
  int z = idx8 >> 8;
  int k8 = (idx8 & 255) << 3;
  uint4 gv = *reinterpret_cast<const uint4*>(Gt + (size_t)z * GK + k8);
  const __nv_bfloat16* gp = reinterpret_cast<const __nv_bfloat16*>(&gv);
  float gf[8];
#pragma unroll
  for (int e = 0; e < 8; e++) gf[e] = __bfloat162float(gp[e]);
#pragma unroll
  for (int d = 0; d < D_N; d++) {
    uint4 ov;
    __nv_bfloat16* op = reinterpret_cast<__nv_bfloat16*>(&ov);
#pragma unroll
    for (int e = 0; e < 8; e++) {
      int k = k8 + e;
      float md = (k < N_N) ? MX[k * D_N + d] : 0.f;
      op[e] = __float2bfloat16(gf[e] * md);
    }
    *reinterpret_cast<uint4*>(W + (size_t)(d * GK + z) * GK + k8) = ov;
  }
}

// denominator planes from P (g_C1 ldc 2048), Q (g_C2 ldc 2048); grid (8, A_N)
__global__ void den4_kernel() {
  int z = blockIdx.x * blockDim.x + threadIdx.x;
  int a = blockIdx.y;
  if (z >= Z_N) return;
  float pr = g_C1[(size_t)a * GK + z], pi = g_C1[(size_t)(1024 + a) * GK + z];
  float qr = g_C2[(size_t)a * GK + z], qi = g_C2[(size_t)(1024 + a) * GK + z];
  float ipp = 1.f / fmaf(pr, pr, pi * pi);
  float iqq = 1.f / fmaf(qr, qr, qi * qi);
  float sre = fmaf(pr, qr, pi * qi);
  float sim = fmaf(pi, qr, -pr * qi);
  float f = ipp * iqq;
  g_den4[(size_t)a * Z_N + z] = make_float4(ipp, iqq, sre * f, -sim * f);
}

// loss over all d from U_all (g_C1 ldc 16384), V_all (g_C2 ldc 16384); grid (64, A_N)
__global__ __launch_bounds__(256) void loss_epi_all_kernel() {
  __shared__ float red[256];
  const int LDB = 8 * GK;
  int tid = threadIdx.x;
  int d = blockIdx.x >> 3;
  int z = (blockIdx.x & 7) * 256 + tid;
  int a = blockIdx.y;
  float lsum = 0.f;
  if (z < Z_N) {
    size_t col = (size_t)d * GK + z;
    float ur = g_C1[(size_t)a * LDB + col], ui = g_C1[(size_t)(1024 + a) * LDB + col];
    float vr = g_C2[(size_t)a * LDB + col], vi = g_C2[(size_t)(1024 + a) * LDB + col];
    float4 dn = g_den4[(size_t)a * Z_N + z];
    float uu = fmaf(ur, ur, ui * ui);
    float vv = fmaf(vr, vr, vi * vi);
    float xr = fmaf(ur, vr, ui * vi);
    float xi = fmaf(ui, vr, -ur * vi);
    lsum = fmaf(uu, dn.x, vv * dn.y) - 2.f * fmaf(xr, dn.z, -xi * dn.w);
  }
  red[tid] = lsum;
  __syncthreads();
  for (int s = 128; s > 0; s >>= 1) {
    if (tid < s) red[tid] += red[tid + s];
    __syncthreads();
  }
  if (tid == 0) atomicAdd(&g_acc, red[0]);
}

__global__ void finalize_kernel(float* out) {
  out[0] = g_acc * (1.f / (float)(A_N * Z_N));
}

// ---------------- launch ----------------
extern "C" void kernel_launch(void* const* d_in, const int* in_sizes, int n_in,
                              void* d_out, int out_size) {
  const float* Mmat  = (const float*)d_in[0];
  const float* Nmat  = (const float*)d_in[1];
  const float* Xmat  = (const float*)d_in[2];
  const float* llam  = (const float*)d_in[3];
  const float* Kz    = (const float*)d_in[4];
  const float* Bz    = (const float*)d_in[5];
  const float* gMN   = (const float*)d_in[6];
  const float* gN    = (const float*)d_in[7];
  const float* alpha = (const float*)d_in[8];
  float* out = (float*)d_out;

  cudaFuncSetAttribute(gemm_cp, cudaFuncAttributeMaxDynamicSharedMemorySize, SMEM_GEMM);

  __nv_bfloat16 *pKbf, *pBzt, *pgNt, *pgNlo, *pgMNt, *pgXt, *pgXlo;
  __nv_bfloat16 *pE1, *pE1lo, *pE2, *pE2lo, *pW1, *pW2;
  float *pC1, *pC2;
  cudaGetSymbolAddress((void**)&pKbf,  g_Kbf);
  cudaGetSymbolAddress((void**)&pBzt,  g_Bzt);
  cudaGetSymbolAddress((void**)&pgNt,  g_gNt);
  cudaGetSymbolAddress((void**)&pgNlo, g_gNlo);
  cudaGetSymbolAddress((void**)&pgMNt, g_gMNt);
  cudaGetSymbolAddress((void**)&pgXt,  g_gXt);
  cudaGetSymbolAddress((void**)&pgXlo, g_gXlo);
  cudaGetSymbolAddress((void**)&pE1,   g_E1st);
  cudaGetSymbolAddress((void**)&pE1lo, g_E1lo);
  cudaGetSymbolAddress((void**)&pE2,   g_E2st);
  cudaGetSymbolAddress((void**)&pE2lo, g_E2lo);
  cudaGetSymbolAddress((void**)&pW1,   g_W1t);
  cudaGetSymbolAddress((void**)&pW2,   g_W2t);
  cudaGetSymbolAddress((void**)&pC1,   g_C1);
  cudaGetSymbolAddress((void**)&pC2,   g_C2);

  dim3 t32(32, 8);
  dim3 g64(64, 64);
  dim3 gg(16, 16);          // square GEMMs: 16 n-tiles x 16 m-tiles
  dim3 ggb(128, 16);        // batched numerators: 128 n-tiles x 16 m-tiles
  dim3 gel(8, A_N);

  zero_acc_kernel<<<1, 1>>>();
  trig_kernel<<<(A_N * GK) / 256, 256>>>(alpha, Nmat, Xmat);
  pad_rows_kernel<<<(48 * GK) / 256, 256>>>();
  cvt_pad_kernel<<<(GK * GK) / 256, 256>>>(Kz);
  transpose_cvt_kernel<<<g64, t32>>>(Bz, pBzt, pBzt, 0);
  transpose_cvt_kernel<<<g64, t32>>>(gN, pgNt, pgNlo, 1);
  transpose_cvt_kernel<<<g64, t32>>>(gMN, pgMNt, pgMNt, 0);

  // Neumann (1 term): T1[i][z] = (K @ B)[i][z]
  gemm_cp<<<gg, 256, SMEM_GEMM>>>(pKbf, pBzt, pKbf, pBzt, pKbf, pBzt, 1, pC1, GK);
  combine_t_kernel<<<g64, t32>>>(Bz, llam);

  // denominators with split-bf16 3-pair accumulation
  gemm_cp<<<gg, 256, SMEM_GEMM>>>(pE1, pgNt, pE1, pgNlo, pE1lo, pgNt, 3, pC1, GK);
  gemm_cp<<<gg, 256, SMEM_GEMM>>>(pE2, pgXt, pE2, pgXlo, pE2lo, pgXt, 3, pC2, GK);
  den4_kernel<<<gel, 256>>>();

  // batched numerators for all 8 d + single fused loss pass
  prepW_all_kernel<<<(GK * GK / 8) / 256, 256>>>(pgMNt, Mmat, pW1);
  prepW_all_kernel<<<(GK * GK / 8) / 256, 256>>>(pgXt, Xmat, pW2);
  gemm_cp<<<ggb, 256, SMEM_GEMM>>>(pE1, pW1, pE1, pW1, pE1, pW1, 1, pC1, 8 * GK);
  gemm_cp<<<ggb, 256, SMEM_GEMM>>>(pE2, pW2, pE2, pW2, pE2, pW2, 1, pC2, 8 * GK);
  loss_epi_all_kernel<<<dim3(64, A_N), 256>>>();
  finalize_kernel<<<1, 1>>>(out);
}